// round 2
// baseline (speedup 1.0000x reference)
#include <cuda_runtime.h>
#include <cuda_bf16.h>
#include <math.h>

// Problem constants
#define B_  4
#define T_  2048
#define D_  1024
#define H_  16
#define DH_ 64

// Scratch (allocation-free rule: __device__ globals)
__device__ float g_qkv[(size_t)B_ * T_ * 3 * D_];   // [B,T,3,H,DH] flattened: e = which*D + h*DH + d
__device__ float g_att[(size_t)B_ * T_ * D_];       // attention output in [B,T,D]

// ---------------------------------------------------------------------------
// GEMM: C[M,N] = A[M,K] @ B[N,K]^T   (fp32, all dims multiples of tiles)
// 128x128 block tile, 256 threads, 8x8 per-thread microtile, BK=16.
// ---------------------------------------------------------------------------
#define GBM 128
#define GBN 128
#define GBK 16

__global__ __launch_bounds__(256) void gemm_tn_kernel(
    const float* __restrict__ A, const float* __restrict__ Bm,
    float* __restrict__ C, int M, int N, int K)
{
    __shared__ float As[GBK][GBM];
    __shared__ float Bs[GBK][GBN];

    const int tid = threadIdx.x;
    const int bm = blockIdx.y * GBM;
    const int bn = blockIdx.x * GBN;
    const int ty = tid >> 4;      // 0..15
    const int tx = tid & 15;      // 0..15

    float acc[8][8];
    #pragma unroll
    for (int i = 0; i < 8; i++)
        #pragma unroll
        for (int j = 0; j < 8; j++) acc[i][j] = 0.0f;

    for (int k0 = 0; k0 < K; k0 += GBK) {
        // Load 128x16 tiles of A and B (each thread: 2 float4 per operand)
        #pragma unroll
        for (int s = 0; s < 2; s++) {
            int slot = tid + s * 256;       // 0..511
            int row  = slot >> 2;           // 0..127
            int c4   = (slot & 3) * 4;      // 0,4,8,12
            float4 av = *(const float4*)(A  + (size_t)(bm + row) * K + k0 + c4);
            As[c4 + 0][row] = av.x; As[c4 + 1][row] = av.y;
            As[c4 + 2][row] = av.z; As[c4 + 3][row] = av.w;
            float4 bv = *(const float4*)(Bm + (size_t)(bn + row) * K + k0 + c4);
            Bs[c4 + 0][row] = bv.x; Bs[c4 + 1][row] = bv.y;
            Bs[c4 + 2][row] = bv.z; Bs[c4 + 3][row] = bv.w;
        }
        __syncthreads();

        #pragma unroll
        for (int k = 0; k < GBK; k++) {
            float a[8], b[8];
            *(float4*)&a[0] = *(const float4*)&As[k][ty * 8];
            *(float4*)&a[4] = *(const float4*)&As[k][ty * 8 + 4];
            *(float4*)&b[0] = *(const float4*)&Bs[k][tx * 8];
            *(float4*)&b[4] = *(const float4*)&Bs[k][tx * 8 + 4];
            #pragma unroll
            for (int i = 0; i < 8; i++)
                #pragma unroll
                for (int j = 0; j < 8; j++)
                    acc[i][j] = fmaf(a[i], b[j], acc[i][j]);
        }
        __syncthreads();
    }

    // Store 8x8 microtile as float4 pairs
    #pragma unroll
    for (int i = 0; i < 8; i++) {
        float* crow = C + (size_t)(bm + ty * 8 + i) * N + bn + tx * 8;
        float4 v0 = make_float4(acc[i][0], acc[i][1], acc[i][2], acc[i][3]);
        float4 v1 = make_float4(acc[i][4], acc[i][5], acc[i][6], acc[i][7]);
        *(float4*)(crow)     = v0;
        *(float4*)(crow + 4) = v1;
    }
}

// ---------------------------------------------------------------------------
// Flash attention (fp32, causal). One block per (q-tile of 64 rows, head, batch).
// 256 threads = 16x16; each thread owns a 4x4 fragment of S and O.
// Online softmax; causal tiles kt>qt skipped entirely.
// ---------------------------------------------------------------------------
#define APAD 65   // 64 + 1 padding (bank-conflict mitigation)
#define ATTN_SMEM (4 * 64 * APAD * 4)   // Qs,Ks,Vs,Ss  = 66560 bytes

__global__ __launch_bounds__(256) void attn_kernel(
    const float* __restrict__ qkv, float* __restrict__ out)
{
    extern __shared__ float sm[];
    float* Qs = sm;                 // [64][APAD]
    float* Ks = Qs + 64 * APAD;
    float* Vs = Ks + 64 * APAD;
    float* Ss = Vs + 64 * APAD;

    const int qt = blockIdx.x;      // 0..31
    const int h  = blockIdx.y;      // 0..15
    const int b  = blockIdx.z;      // 0..3
    const int tid = threadIdx.x;
    const int ty = tid >> 4;        // row group 0..15 -> rows ty*4..ty*4+3
    const int tx = tid & 15;        // col group 0..15 -> cols tx*4..tx*4+3

    const float scale = 0.125f;     // 1/sqrt(64)

    // Load Q tile (scaled). 64x64 floats = 1024 float4; 4 per thread.
    #pragma unroll
    for (int s = 0; s < 4; s++) {
        int slot = tid + s * 256;   // 0..1023
        int r  = slot >> 4;         // 0..63
        int c4 = (slot & 15) * 4;   // 0..60
        const float* src = qkv + ((size_t)(b * T_ + qt * 64 + r) * (3 * D_)) + h * DH_ + c4;
        float4 v = *(const float4*)src;
        float* dst = &Qs[r * APAD + c4];
        dst[0] = v.x * scale; dst[1] = v.y * scale;
        dst[2] = v.z * scale; dst[3] = v.w * scale;
    }

    float m_i[4], l_i[4], o[4][4];
    #pragma unroll
    for (int i = 0; i < 4; i++) {
        m_i[i] = -1e30f;
        l_i[i] = 0.0f;
        #pragma unroll
        for (int j = 0; j < 4; j++) o[i][j] = 0.0f;
    }
    __syncthreads();

    for (int kt = 0; kt <= qt; kt++) {
        // Load K and V tiles (64x64 each)
        #pragma unroll
        for (int s = 0; s < 4; s++) {
            int slot = tid + s * 256;
            int r  = slot >> 4;
            int c4 = (slot & 15) * 4;
            size_t base = (size_t)(b * T_ + kt * 64 + r) * (3 * D_) + h * DH_ + c4;
            float4 kv = *(const float4*)(qkv + base + D_);        // K slab
            float4 vv = *(const float4*)(qkv + base + 2 * D_);    // V slab
            float* kd = &Ks[r * APAD + c4];
            kd[0] = kv.x; kd[1] = kv.y; kd[2] = kv.z; kd[3] = kv.w;
            float* vd = &Vs[r * APAD + c4];
            vd[0] = vv.x; vd[1] = vv.y; vd[2] = vv.z; vd[3] = vv.w;
        }
        __syncthreads();

        // S fragment: S[ty*4+i][tx*4+j] = sum_d Q[row][d] * K[col][d]
        float sfr[4][4];
        #pragma unroll
        for (int i = 0; i < 4; i++)
            #pragma unroll
            for (int j = 0; j < 4; j++) sfr[i][j] = 0.0f;

        #pragma unroll 4
        for (int d = 0; d < 64; d++) {
            float qv[4], kv[4];
            #pragma unroll
            for (int i = 0; i < 4; i++) qv[i] = Qs[(ty * 4 + i) * APAD + d];
            #pragma unroll
            for (int j = 0; j < 4; j++) kv[j] = Ks[(tx * 4 + j) * APAD + d];
            #pragma unroll
            for (int i = 0; i < 4; i++)
                #pragma unroll
                for (int j = 0; j < 4; j++)
                    sfr[i][j] = fmaf(qv[i], kv[j], sfr[i][j]);
        }

        // Causal mask inside diagonal tile
        if (kt == qt) {
            #pragma unroll
            for (int i = 0; i < 4; i++)
                #pragma unroll
                for (int j = 0; j < 4; j++)
                    if (tx * 4 + j > ty * 4 + i) sfr[i][j] = -1e30f;
        }

        // Online softmax per row (reduction across the 16 tx lanes)
        #pragma unroll
        for (int i = 0; i < 4; i++) {
            float rm = sfr[i][0];
            #pragma unroll
            for (int j = 1; j < 4; j++) rm = fmaxf(rm, sfr[i][j]);
            #pragma unroll
            for (int off = 8; off > 0; off >>= 1)
                rm = fmaxf(rm, __shfl_xor_sync(0xffffffffu, rm, off));

            float m_new = fmaxf(m_i[i], rm);
            float alpha = __expf(m_i[i] - m_new);

            float rs = 0.0f;
            #pragma unroll
            for (int j = 0; j < 4; j++) {
                float p = __expf(sfr[i][j] - m_new);
                sfr[i][j] = p;
                rs += p;
            }
            #pragma unroll
            for (int off = 8; off > 0; off >>= 1)
                rs += __shfl_xor_sync(0xffffffffu, rs, off);

            l_i[i] = l_i[i] * alpha + rs;
            m_i[i] = m_new;
            #pragma unroll
            for (int j = 0; j < 4; j++) o[i][j] *= alpha;

            // stage P row segment to smem for the PV matmul
            float* sp = &Ss[(ty * 4 + i) * APAD + tx * 4];
            sp[0] = sfr[i][0]; sp[1] = sfr[i][1]; sp[2] = sfr[i][2]; sp[3] = sfr[i][3];
        }
        __syncthreads();

        // O += P @ V
        #pragma unroll 4
        for (int c = 0; c < 64; c++) {
            float pv[4], vv[4];
            #pragma unroll
            for (int i = 0; i < 4; i++) pv[i] = Ss[(ty * 4 + i) * APAD + c];
            #pragma unroll
            for (int j = 0; j < 4; j++) vv[j] = Vs[c * APAD + tx * 4 + j];
            #pragma unroll
            for (int i = 0; i < 4; i++)
                #pragma unroll
                for (int j = 0; j < 4; j++)
                    o[i][j] = fmaf(pv[i], vv[j], o[i][j]);
        }
        __syncthreads();  // protect Ks/Vs/Ss before next iteration's loads
    }

    // Epilogue: normalize and write to [B,T,D] layout
    #pragma unroll
    for (int i = 0; i < 4; i++) {
        float inv_l = 1.0f / l_i[i];
        int t = qt * 64 + ty * 4 + i;
        float* dst = out + (size_t)(b * T_ + t) * D_ + h * DH_ + tx * 4;
        float4 v = make_float4(o[i][0] * inv_l, o[i][1] * inv_l,
                               o[i][2] * inv_l, o[i][3] * inv_l);
        *(float4*)dst = v;
    }
}

// ---------------------------------------------------------------------------
// Launch
// ---------------------------------------------------------------------------
extern "C" void kernel_launch(void* const* d_in, const int* in_sizes, int n_in,
                              void* d_out, int out_size)
{
    const float* x      = (const float*)d_in[0];   // [B,T,D]
    const float* w_attn = (const float*)d_in[1];   // [3D, D]
    const float* w_proj = (const float*)d_in[2];   // [D, D]
    float* out = (float*)d_out;                    // [B,T,D]

    float* qkv = nullptr;
    float* yat = nullptr;
    cudaGetSymbolAddress((void**)&qkv, g_qkv);
    cudaGetSymbolAddress((void**)&yat, g_att);

    cudaFuncSetAttribute(attn_kernel,
                         cudaFuncAttributeMaxDynamicSharedMemorySize, ATTN_SMEM);

    const int M = B_ * T_;   // 8192

    // 1) qkv = x @ w_attn^T   [8192, 3072]
    gemm_tn_kernel<<<dim3((3 * D_) / GBN, M / GBM), 256>>>(
        x, w_attn, qkv, M, 3 * D_, D_);

    // 2) flash attention -> g_att [B,T,D]
    attn_kernel<<<dim3(T_ / 64, H_, B_), 256, ATTN_SMEM>>>(qkv, yat);

    // 3) out = g_att @ w_proj^T   [8192, 1024]
    gemm_tn_kernel<<<dim3(D_ / GBN, M / GBM), 256>>>(
        yat, w_proj, out, M, D_, D_);
}

// round 5
// speedup vs baseline: 1.3773x; 1.3773x over previous
#include <cuda_runtime.h>
#include <cuda_bf16.h>
#include <math.h>
#include <stdint.h>

// Problem constants
#define B_  4
#define T_  2048
#define D_  1024
#define H_  16
#define DH_ 64

// ---------------------------------------------------------------------------
// Scratch (allocation-free rule: __device__ globals)
// ---------------------------------------------------------------------------
__device__ float g_qkv[(size_t)B_ * T_ * 3 * D_];   // [B,T,3D] fp32
__device__ float g_att[(size_t)B_ * T_ * D_];       // attention out [B,T,D] fp32

// bf16 hi/lo split operands
__device__ unsigned short g_xhi[(size_t)B_ * T_ * D_];
__device__ unsigned short g_xlo[(size_t)B_ * T_ * D_];
__device__ unsigned short g_wahi[(size_t)3 * D_ * D_];
__device__ unsigned short g_walo[(size_t)3 * D_ * D_];
__device__ unsigned short g_wphi[(size_t)D_ * D_];
__device__ unsigned short g_wplo[(size_t)D_ * D_];
__device__ unsigned short g_yhi[(size_t)B_ * T_ * D_];
__device__ unsigned short g_ylo[(size_t)B_ * T_ * D_];

// ---------------------------------------------------------------------------
// mma.sync m16n8k16 bf16 (baseline PTX, works on sm_103 without 'a' feature)
// ---------------------------------------------------------------------------
__device__ __forceinline__ void mma_bf16_16816(
    float c[4], uint32_t a0, uint32_t a1, uint32_t a2, uint32_t a3,
    uint32_t b0, uint32_t b1)
{
    asm volatile(
        "mma.sync.aligned.m16n8k16.row.col.f32.bf16.bf16.f32 "
        "{%0,%1,%2,%3}, {%4,%5,%6,%7}, {%8,%9}, {%0,%1,%2,%3};"
        : "+f"(c[0]), "+f"(c[1]), "+f"(c[2]), "+f"(c[3])
        : "r"(a0), "r"(a1), "r"(a2), "r"(a3), "r"(b0), "r"(b1));
}

// ---------------------------------------------------------------------------
// Split fp32 -> bf16 (hi, lo) pair. a ~= hi + lo (16-bit effective mantissa).
// ---------------------------------------------------------------------------
__global__ __launch_bounds__(256) void split_bf16_kernel(
    const float* __restrict__ in, unsigned short* __restrict__ hi,
    unsigned short* __restrict__ lo, int n4)
{
    int i = blockIdx.x * 256 + threadIdx.x;
    if (i >= n4) return;
    float4 v = ((const float4*)in)[i];
    float a[4] = {v.x, v.y, v.z, v.w};
    unsigned short hbits[4], lbits[4];
    #pragma unroll
    for (int j = 0; j < 4; j++) {
        __nv_bfloat16 h = __float2bfloat16(a[j]);
        float hf = __bfloat162float(h);
        __nv_bfloat16 l = __float2bfloat16(a[j] - hf);
        hbits[j] = __bfloat16_as_ushort(h);
        lbits[j] = __bfloat16_as_ushort(l);
    }
    uint2 hp, lp;
    hp.x = (uint32_t)hbits[0] | ((uint32_t)hbits[1] << 16);
    hp.y = (uint32_t)hbits[2] | ((uint32_t)hbits[3] << 16);
    lp.x = (uint32_t)lbits[0] | ((uint32_t)lbits[1] << 16);
    lp.y = (uint32_t)lbits[2] | ((uint32_t)lbits[3] << 16);
    ((uint2*)hi)[i] = hp;
    ((uint2*)lo)[i] = lp;
}

// ---------------------------------------------------------------------------
// HMMA GEMM: C[M,N] = A[M,K] @ B[N,K]^T, A/B as bf16 (hi,lo) pairs.
// Accumulates hi*hi + hi*lo + lo*hi in fp32 registers.
// Block tile 128x128, BK=32, 256 threads = 8 warps (2 x 4), warp tile 64x32.
// smem rows padded to 40 bf16 (80B) -> conflict-free fragment loads.
// ---------------------------------------------------------------------------
#define KPAD 40

__global__ __launch_bounds__(256) void gemm_mma_kernel(
    const unsigned short* __restrict__ Ahi, const unsigned short* __restrict__ Alo,
    const unsigned short* __restrict__ Bhi, const unsigned short* __restrict__ Blo,
    float* __restrict__ C, int M, int N, int K)
{
    __shared__ unsigned short Ash[128][KPAD];
    __shared__ unsigned short Asl[128][KPAD];
    __shared__ unsigned short Bsh[128][KPAD];
    __shared__ unsigned short Bsl[128][KPAD];

    const int tid = threadIdx.x;
    const int wid = tid >> 5;
    const int lane = tid & 31;
    const int g = lane >> 2;      // 0..7
    const int t = lane & 3;       // 0..3
    const int warp_m = (wid >> 2) * 64;   // 0 or 64
    const int warp_n = (wid & 3) * 32;    // 0,32,64,96
    const int bm = blockIdx.y * 128;
    const int bn = blockIdx.x * 128;

    float acc[4][4][4];   // [mfrag][nfrag][c0..c3]
    #pragma unroll
    for (int i = 0; i < 4; i++)
        #pragma unroll
        for (int j = 0; j < 4; j++)
            #pragma unroll
            for (int r = 0; r < 4; r++) acc[i][j][r] = 0.0f;

    for (int k0 = 0; k0 < K; k0 += 32) {
        // Load 128x32 bf16 tiles (64B/row as 4x16B chunks): 512 chunks per
        // array, 2 per thread per array.
        #pragma unroll
        for (int c = 0; c < 2; c++) {
            int ch  = tid + c * 256;      // 0..511
            int row = ch >> 2;            // 0..127
            int off = (ch & 3) * 8;       // bf16 offset within row: 0,8,16,24
            size_t ga = (size_t)(bm + row) * K + k0 + off;
            size_t gb = (size_t)(bn + row) * K + k0 + off;
            *(uint4*)&Ash[row][off] = *(const uint4*)(Ahi + ga);
            *(uint4*)&Asl[row][off] = *(const uint4*)(Alo + ga);
            *(uint4*)&Bsh[row][off] = *(const uint4*)(Bhi + gb);
            *(uint4*)&Bsl[row][off] = *(const uint4*)(Blo + gb);
        }
        __syncthreads();

        #pragma unroll
        for (int ks = 0; ks < 2; ks++) {
            const int kb = ks * 16;

            // B fragments: n8k16 -> 2 regs. b0: [n0+g][kb+t*2], b1: +8 in k.
            uint32_t bh[4][2], bl[4][2];
            #pragma unroll
            for (int nf = 0; nf < 4; nf++) {
                int br = warp_n + nf * 8 + g;
                bh[nf][0] = *(const uint32_t*)&Bsh[br][kb + t * 2];
                bh[nf][1] = *(const uint32_t*)&Bsh[br][kb + 8 + t * 2];
                bl[nf][0] = *(const uint32_t*)&Bsl[br][kb + t * 2];
                bl[nf][1] = *(const uint32_t*)&Bsl[br][kb + 8 + t * 2];
            }

            // A fragments: m16k16 -> 4 regs.
            uint32_t ah[4][4], al[4][4];
            #pragma unroll
            for (int mf = 0; mf < 4; mf++) {
                int ar = warp_m + mf * 16 + g;
                ah[mf][0] = *(const uint32_t*)&Ash[ar][kb + t * 2];
                ah[mf][1] = *(const uint32_t*)&Ash[ar + 8][kb + t * 2];
                ah[mf][2] = *(const uint32_t*)&Ash[ar][kb + 8 + t * 2];
                ah[mf][3] = *(const uint32_t*)&Ash[ar + 8][kb + 8 + t * 2];
                al[mf][0] = *(const uint32_t*)&Asl[ar][kb + t * 2];
                al[mf][1] = *(const uint32_t*)&Asl[ar + 8][kb + t * 2];
                al[mf][2] = *(const uint32_t*)&Asl[ar][kb + 8 + t * 2];
                al[mf][3] = *(const uint32_t*)&Asl[ar + 8][kb + 8 + t * 2];
            }

            #pragma unroll
            for (int mf = 0; mf < 4; mf++)
                #pragma unroll
                for (int nf = 0; nf < 4; nf++) {
                    mma_bf16_16816(acc[mf][nf],
                                   ah[mf][0], ah[mf][1], ah[mf][2], ah[mf][3],
                                   bh[nf][0], bh[nf][1]);
                    mma_bf16_16816(acc[mf][nf],
                                   ah[mf][0], ah[mf][1], ah[mf][2], ah[mf][3],
                                   bl[nf][0], bl[nf][1]);
                    mma_bf16_16816(acc[mf][nf],
                                   al[mf][0], al[mf][1], al[mf][2], al[mf][3],
                                   bh[nf][0], bh[nf][1]);
                }
        }
        __syncthreads();
    }

    // Epilogue: c0,c1 at (row g, col t*2); c2,c3 at (row g+8).
    #pragma unroll
    for (int mf = 0; mf < 4; mf++) {
        #pragma unroll
        for (int nf = 0; nf < 4; nf++) {
            int row = bm + warp_m + mf * 16 + g;
            int col = bn + warp_n + nf * 8 + t * 2;
            float2 v01 = make_float2(acc[mf][nf][0], acc[mf][nf][1]);
            float2 v23 = make_float2(acc[mf][nf][2], acc[mf][nf][3]);
            *(float2*)(C + (size_t)row * N + col)       = v01;
            *(float2*)(C + (size_t)(row + 8) * N + col) = v23;
        }
    }
}

// ---------------------------------------------------------------------------
// Flash attention (fp32, causal) — unchanged (passing, ~1ms; next target).
// ---------------------------------------------------------------------------
#define APAD 65
#define ATTN_SMEM (4 * 64 * APAD * 4)

__global__ __launch_bounds__(256) void attn_kernel(
    const float* __restrict__ qkv, float* __restrict__ out)
{
    extern __shared__ float sm[];
    float* Qs = sm;
    float* Ks = Qs + 64 * APAD;
    float* Vs = Ks + 64 * APAD;
    float* Ss = Vs + 64 * APAD;

    const int qt = blockIdx.x;
    const int h  = blockIdx.y;
    const int b  = blockIdx.z;
    const int tid = threadIdx.x;
    const int ty = tid >> 4;
    const int tx = tid & 15;

    const float scale = 0.125f;

    #pragma unroll
    for (int s = 0; s < 4; s++) {
        int slot = tid + s * 256;
        int r  = slot >> 4;
        int c4 = (slot & 15) * 4;
        const float* src = qkv + ((size_t)(b * T_ + qt * 64 + r) * (3 * D_)) + h * DH_ + c4;
        float4 v = *(const float4*)src;
        float* dst = &Qs[r * APAD + c4];
        dst[0] = v.x * scale; dst[1] = v.y * scale;
        dst[2] = v.z * scale; dst[3] = v.w * scale;
    }

    float m_i[4], l_i[4], o[4][4];
    #pragma unroll
    for (int i = 0; i < 4; i++) {
        m_i[i] = -1e30f;
        l_i[i] = 0.0f;
        #pragma unroll
        for (int j = 0; j < 4; j++) o[i][j] = 0.0f;
    }
    __syncthreads();

    for (int kt = 0; kt <= qt; kt++) {
        #pragma unroll
        for (int s = 0; s < 4; s++) {
            int slot = tid + s * 256;
            int r  = slot >> 4;
            int c4 = (slot & 15) * 4;
            size_t base = (size_t)(b * T_ + kt * 64 + r) * (3 * D_) + h * DH_ + c4;
            float4 kv = *(const float4*)(qkv + base + D_);
            float4 vv = *(const float4*)(qkv + base + 2 * D_);
            float* kd = &Ks[r * APAD + c4];
            kd[0] = kv.x; kd[1] = kv.y; kd[2] = kv.z; kd[3] = kv.w;
            float* vd = &Vs[r * APAD + c4];
            vd[0] = vv.x; vd[1] = vv.y; vd[2] = vv.z; vd[3] = vv.w;
        }
        __syncthreads();

        float sfr[4][4];
        #pragma unroll
        for (int i = 0; i < 4; i++)
            #pragma unroll
            for (int j = 0; j < 4; j++) sfr[i][j] = 0.0f;

        #pragma unroll 4
        for (int d = 0; d < 64; d++) {
            float qv[4], kv[4];
            #pragma unroll
            for (int i = 0; i < 4; i++) qv[i] = Qs[(ty * 4 + i) * APAD + d];
            #pragma unroll
            for (int j = 0; j < 4; j++) kv[j] = Ks[(tx * 4 + j) * APAD + d];
            #pragma unroll
            for (int i = 0; i < 4; i++)
                #pragma unroll
                for (int j = 0; j < 4; j++)
                    sfr[i][j] = fmaf(qv[i], kv[j], sfr[i][j]);
        }

        if (kt == qt) {
            #pragma unroll
            for (int i = 0; i < 4; i++)
                #pragma unroll
                for (int j = 0; j < 4; j++)
                    if (tx * 4 + j > ty * 4 + i) sfr[i][j] = -1e30f;
        }

        #pragma unroll
        for (int i = 0; i < 4; i++) {
            float rm = sfr[i][0];
            #pragma unroll
            for (int j = 1; j < 4; j++) rm = fmaxf(rm, sfr[i][j]);
            #pragma unroll
            for (int off = 8; off > 0; off >>= 1)
                rm = fmaxf(rm, __shfl_xor_sync(0xffffffffu, rm, off));

            float m_new = fmaxf(m_i[i], rm);
            float alpha = __expf(m_i[i] - m_new);

            float rs = 0.0f;
            #pragma unroll
            for (int j = 0; j < 4; j++) {
                float p = __expf(sfr[i][j] - m_new);
                sfr[i][j] = p;
                rs += p;
            }
            #pragma unroll
            for (int off = 8; off > 0; off >>= 1)
                rs += __shfl_xor_sync(0xffffffffu, rs, off);

            l_i[i] = l_i[i] * alpha + rs;
            m_i[i] = m_new;
            #pragma unroll
            for (int j = 0; j < 4; j++) o[i][j] *= alpha;

            float* sp = &Ss[(ty * 4 + i) * APAD + tx * 4];
            sp[0] = sfr[i][0]; sp[1] = sfr[i][1]; sp[2] = sfr[i][2]; sp[3] = sfr[i][3];
        }
        __syncthreads();

        #pragma unroll 4
        for (int c = 0; c < 64; c++) {
            float pv[4], vv[4];
            #pragma unroll
            for (int i = 0; i < 4; i++) pv[i] = Ss[(ty * 4 + i) * APAD + c];
            #pragma unroll
            for (int j = 0; j < 4; j++) vv[j] = Vs[c * APAD + tx * 4 + j];
            #pragma unroll
            for (int i = 0; i < 4; i++)
                #pragma unroll
                for (int j = 0; j < 4; j++)
                    o[i][j] = fmaf(pv[i], vv[j], o[i][j]);
        }
        __syncthreads();
    }

    #pragma unroll
    for (int i = 0; i < 4; i++) {
        float inv_l = 1.0f / l_i[i];
        int t = qt * 64 + ty * 4 + i;
        float* dst = out + (size_t)(b * T_ + t) * D_ + h * DH_ + tx * 4;
        float4 v = make_float4(o[i][0] * inv_l, o[i][1] * inv_l,
                               o[i][2] * inv_l, o[i][3] * inv_l);
        *(float4*)dst = v;
    }
}

// ---------------------------------------------------------------------------
// Launch
// ---------------------------------------------------------------------------
extern "C" void kernel_launch(void* const* d_in, const int* in_sizes, int n_in,
                              void* d_out, int out_size)
{
    const float* x      = (const float*)d_in[0];   // [B,T,D]
    const float* w_attn = (const float*)d_in[1];   // [3D, D]
    const float* w_proj = (const float*)d_in[2];   // [D, D]
    float* out = (float*)d_out;                    // [B,T,D]

    float *qkv, *yat;
    unsigned short *xhi, *xlo, *wahi, *walo, *wphi, *wplo, *yhi, *ylo;
    cudaGetSymbolAddress((void**)&qkv,  g_qkv);
    cudaGetSymbolAddress((void**)&yat,  g_att);
    cudaGetSymbolAddress((void**)&xhi,  g_xhi);
    cudaGetSymbolAddress((void**)&xlo,  g_xlo);
    cudaGetSymbolAddress((void**)&wahi, g_wahi);
    cudaGetSymbolAddress((void**)&walo, g_walo);
    cudaGetSymbolAddress((void**)&wphi, g_wphi);
    cudaGetSymbolAddress((void**)&wplo, g_wplo);
    cudaGetSymbolAddress((void**)&yhi,  g_yhi);
    cudaGetSymbolAddress((void**)&ylo,  g_ylo);

    cudaFuncSetAttribute(attn_kernel,
                         cudaFuncAttributeMaxDynamicSharedMemorySize, ATTN_SMEM);

    const int M = B_ * T_;   // 8192

    // Split inputs to bf16 hi/lo
    {
        int n4x = (B_ * T_ * D_) / 4;
        int n4a = (3 * D_ * D_) / 4;
        int n4p = (D_ * D_) / 4;
        split_bf16_kernel<<<(n4x + 255) / 256, 256>>>(x, xhi, xlo, n4x);
        split_bf16_kernel<<<(n4a + 255) / 256, 256>>>(w_attn, wahi, walo, n4a);
        split_bf16_kernel<<<(n4p + 255) / 256, 256>>>(w_proj, wphi, wplo, n4p);
    }

    // 1) qkv = x @ w_attn^T   [8192, 3072]
    gemm_mma_kernel<<<dim3((3 * D_) / 128, M / 128), 256>>>(
        xhi, xlo, wahi, walo, qkv, M, 3 * D_, D_);

    // 2) flash attention -> g_att [B,T,D]
    attn_kernel<<<dim3(T_ / 64, H_, B_), 256, ATTN_SMEM>>>(qkv, yat);

    // split attention output
    {
        int n4y = (B_ * T_ * D_) / 4;
        split_bf16_kernel<<<(n4y + 255) / 256, 256>>>(yat, yhi, ylo, n4y);
    }

    // 3) out = y @ w_proj^T   [8192, 1024]
    gemm_mma_kernel<<<dim3(D_ / 128, M / 128), 256>>>(
        yhi, ylo, wphi, wplo, out, M, D_, D_);
}

// round 6
// speedup vs baseline: 2.7375x; 1.9875x over previous
#include <cuda_runtime.h>
#include <cuda_bf16.h>
#include <math.h>
#include <stdint.h>

// Problem constants
#define B_  4
#define T_  2048
#define D_  1024
#define H_  16
#define DH_ 64

typedef unsigned short u16;

// ---------------------------------------------------------------------------
// Scratch (allocation-free rule: __device__ globals)
// ---------------------------------------------------------------------------
__device__ u16 g_xhi[(size_t)B_ * T_ * D_];
__device__ u16 g_xlo[(size_t)B_ * T_ * D_];
__device__ u16 g_wahi[(size_t)3 * D_ * D_];
__device__ u16 g_walo[(size_t)3 * D_ * D_];
__device__ u16 g_wphi[(size_t)D_ * D_];
__device__ u16 g_wplo[(size_t)D_ * D_];
__device__ u16 g_qkvh[(size_t)B_ * T_ * 3 * D_];   // qkv hi (bf16 bits)
__device__ u16 g_qkvl[(size_t)B_ * T_ * 3 * D_];   // qkv lo
__device__ u16 g_yhi[(size_t)B_ * T_ * D_];
__device__ u16 g_ylo[(size_t)B_ * T_ * D_];

// ---------------------------------------------------------------------------
// Helpers
// ---------------------------------------------------------------------------
__device__ __forceinline__ uint32_t smem_u32(const void* p) {
    uint32_t a;
    asm("{ .reg .u64 t; cvta.to.shared.u64 t, %1; cvt.u32.u64 %0, t; }"
        : "=r"(a) : "l"(p));
    return a;
}

__device__ __forceinline__ void mma_bf16_16816(
    float c[4], uint32_t a0, uint32_t a1, uint32_t a2, uint32_t a3,
    uint32_t b0, uint32_t b1)
{
    asm volatile(
        "mma.sync.aligned.m16n8k16.row.col.f32.bf16.bf16.f32 "
        "{%0,%1,%2,%3}, {%4,%5,%6,%7}, {%8,%9}, {%0,%1,%2,%3};"
        : "+f"(c[0]), "+f"(c[1]), "+f"(c[2]), "+f"(c[3])
        : "r"(a0), "r"(a1), "r"(a2), "r"(a3), "r"(b0), "r"(b1));
}

// split two floats into packed bf16 hi (ret) and lo (out param)
__device__ __forceinline__ uint32_t split_pack(float f0, float f1, uint32_t& lop) {
    __nv_bfloat16 h0 = __float2bfloat16(f0);
    __nv_bfloat16 h1 = __float2bfloat16(f1);
    __nv_bfloat16 l0 = __float2bfloat16(f0 - __bfloat162float(h0));
    __nv_bfloat16 l1 = __float2bfloat16(f1 - __bfloat162float(h1));
    lop = (uint32_t)__bfloat16_as_ushort(l0) | ((uint32_t)__bfloat16_as_ushort(l1) << 16);
    return (uint32_t)__bfloat16_as_ushort(h0) | ((uint32_t)__bfloat16_as_ushort(h1) << 16);
}

#define CP_ASYNC16(dst, src) \
    asm volatile("cp.async.cg.shared.global [%0], [%1], 16;" :: "r"(dst), "l"(src))
#define CP_COMMIT() asm volatile("cp.async.commit_group;")
#define CP_WAIT1()  asm volatile("cp.async.wait_group 1;")
#define CP_WAIT0()  asm volatile("cp.async.wait_group 0;")

// ---------------------------------------------------------------------------
// Split fp32 -> bf16 (hi, lo) pair
// ---------------------------------------------------------------------------
__global__ __launch_bounds__(256) void split_bf16_kernel(
    const float* __restrict__ in, u16* __restrict__ hi,
    u16* __restrict__ lo, int n4)
{
    int i = blockIdx.x * 256 + threadIdx.x;
    if (i >= n4) return;
    float4 v = ((const float4*)in)[i];
    uint32_t lp0, lp1;
    uint32_t hp0 = split_pack(v.x, v.y, lp0);
    uint32_t hp1 = split_pack(v.z, v.w, lp1);
    ((uint2*)hi)[i] = make_uint2(hp0, hp1);
    ((uint2*)lo)[i] = make_uint2(lp0, lp1);
}

// ---------------------------------------------------------------------------
// HMMA GEMM with cp.async double buffering.
// C[M,N] = A[M,K] @ B[N,K]^T with hi/lo split accumulation.
// Block tile 128x128, BK=32, 256 threads = 8 warps (2x4), warp tile 64x32.
// SPLIT_OUT: write C as bf16 hi/lo pair instead of fp32.
// ---------------------------------------------------------------------------
#define KPADB 80          // bytes per smem row (40 shorts)
#define ARR_SZ 10240      // 128 * 80
#define STAGE_SZ 40960    // 4 arrays
#define GEMM_SMEM (2 * STAGE_SZ)

template<bool SPLIT_OUT>
__global__ __launch_bounds__(256) void gemm_mma_db(
    const u16* __restrict__ Ahi, const u16* __restrict__ Alo,
    const u16* __restrict__ Bhi, const u16* __restrict__ Blo,
    float* __restrict__ Cf, u16* __restrict__ Chi, u16* __restrict__ Clo,
    int M, int N, int K)
{
    extern __shared__ char smc[];
    const uint32_t sb = smem_u32(smc);

    const int tid = threadIdx.x;
    const int wid = tid >> 5;
    const int lane = tid & 31;
    const int g = lane >> 2;
    const int t = lane & 3;
    const int warp_m = (wid >> 2) * 64;
    const int warp_n = (wid & 3) * 32;
    const int bm = blockIdx.y * 128;
    const int bn = blockIdx.x * 128;

    float acc[4][4][4];
    #pragma unroll
    for (int i = 0; i < 4; i++)
        #pragma unroll
        for (int j = 0; j < 4; j++)
            #pragma unroll
            for (int r = 0; r < 4; r++) acc[i][j][r] = 0.0f;

    auto prefetch = [&](int k0, int s) {
        #pragma unroll
        for (int c = 0; c < 2; c++) {
            int ch = tid + c * 256;          // 0..511
            int row = ch >> 2;
            int cq = ch & 3;
            uint32_t so = sb + s * STAGE_SZ + row * KPADB + cq * 16;
            size_t ga = (size_t)(bm + row) * K + k0 + cq * 8;
            size_t gb = (size_t)(bn + row) * K + k0 + cq * 8;
            CP_ASYNC16(so + 0 * ARR_SZ, Ahi + ga);
            CP_ASYNC16(so + 1 * ARR_SZ, Alo + ga);
            CP_ASYNC16(so + 2 * ARR_SZ, Bhi + gb);
            CP_ASYNC16(so + 3 * ARR_SZ, Blo + gb);
        }
        CP_COMMIT();
    };

    const int nt = K / 32;
    prefetch(0, 0);

    for (int ti = 0; ti < nt; ti++) {
        if (ti + 1 < nt) { prefetch((ti + 1) * 32, (ti + 1) & 1); CP_WAIT1(); }
        else             { CP_WAIT0(); }
        __syncthreads();

        char* st = smc + (ti & 1) * STAGE_SZ;
        const u16* Ash = (const u16*)(st + 0 * ARR_SZ);
        const u16* Asl = (const u16*)(st + 1 * ARR_SZ);
        const u16* Bsh = (const u16*)(st + 2 * ARR_SZ);
        const u16* Bsl = (const u16*)(st + 3 * ARR_SZ);
        const int RS = KPADB / 2;   // row stride in shorts (40)

        #pragma unroll
        for (int ks = 0; ks < 2; ks++) {
            const int kb = ks * 16;

            uint32_t bh[4][2], bl[4][2];
            #pragma unroll
            for (int nf = 0; nf < 4; nf++) {
                int br = warp_n + nf * 8 + g;
                bh[nf][0] = *(const uint32_t*)&Bsh[br * RS + kb + t * 2];
                bh[nf][1] = *(const uint32_t*)&Bsh[br * RS + kb + 8 + t * 2];
                bl[nf][0] = *(const uint32_t*)&Bsl[br * RS + kb + t * 2];
                bl[nf][1] = *(const uint32_t*)&Bsl[br * RS + kb + 8 + t * 2];
            }

            uint32_t ah[4][4], al[4][4];
            #pragma unroll
            for (int mf = 0; mf < 4; mf++) {
                int ar = warp_m + mf * 16 + g;
                ah[mf][0] = *(const uint32_t*)&Ash[ar * RS + kb + t * 2];
                ah[mf][1] = *(const uint32_t*)&Ash[(ar + 8) * RS + kb + t * 2];
                ah[mf][2] = *(const uint32_t*)&Ash[ar * RS + kb + 8 + t * 2];
                ah[mf][3] = *(const uint32_t*)&Ash[(ar + 8) * RS + kb + 8 + t * 2];
                al[mf][0] = *(const uint32_t*)&Asl[ar * RS + kb + t * 2];
                al[mf][1] = *(const uint32_t*)&Asl[(ar + 8) * RS + kb + t * 2];
                al[mf][2] = *(const uint32_t*)&Asl[ar * RS + kb + 8 + t * 2];
                al[mf][3] = *(const uint32_t*)&Asl[(ar + 8) * RS + kb + 8 + t * 2];
            }

            #pragma unroll
            for (int mf = 0; mf < 4; mf++)
                #pragma unroll
                for (int nf = 0; nf < 4; nf++) {
                    mma_bf16_16816(acc[mf][nf],
                                   ah[mf][0], ah[mf][1], ah[mf][2], ah[mf][3],
                                   bh[nf][0], bh[nf][1]);
                    mma_bf16_16816(acc[mf][nf],
                                   ah[mf][0], ah[mf][1], ah[mf][2], ah[mf][3],
                                   bl[nf][0], bl[nf][1]);
                    mma_bf16_16816(acc[mf][nf],
                                   al[mf][0], al[mf][1], al[mf][2], al[mf][3],
                                   bh[nf][0], bh[nf][1]);
                }
        }
        __syncthreads();
    }

    #pragma unroll
    for (int mf = 0; mf < 4; mf++) {
        #pragma unroll
        for (int nf = 0; nf < 4; nf++) {
            int row = bm + warp_m + mf * 16 + g;
            int col = bn + warp_n + nf * 8 + t * 2;
            if (SPLIT_OUT) {
                uint32_t lp;
                uint32_t hp = split_pack(acc[mf][nf][0], acc[mf][nf][1], lp);
                *(uint32_t*)&Chi[(size_t)row * N + col] = hp;
                *(uint32_t*)&Clo[(size_t)row * N + col] = lp;
                hp = split_pack(acc[mf][nf][2], acc[mf][nf][3], lp);
                *(uint32_t*)&Chi[(size_t)(row + 8) * N + col] = hp;
                *(uint32_t*)&Clo[(size_t)(row + 8) * N + col] = lp;
            } else {
                *(float2*)(Cf + (size_t)row * N + col) =
                    make_float2(acc[mf][nf][0], acc[mf][nf][1]);
                *(float2*)(Cf + (size_t)(row + 8) * N + col) =
                    make_float2(acc[mf][nf][2], acc[mf][nf][3]);
            }
        }
    }
}

// ---------------------------------------------------------------------------
// Flash attention on HMMA with hi/lo split everywhere.
// Block: 128 threads (4 warps), one 64-row q-tile per (qt, h, b).
// Warp w owns rows w*16..w*16+15. S tile 64x64 per kt iteration.
// ---------------------------------------------------------------------------
#define QROWB 144                 // 72 shorts per padded row
#define TILE_SZ (64 * QROWB)      // 9216 bytes
#define A_QH (0 * TILE_SZ)
#define A_QL (1 * TILE_SZ)
#define A_KH (2 * TILE_SZ)
#define A_KL (3 * TILE_SZ)
#define A_VH (4 * TILE_SZ)
#define A_VL (5 * TILE_SZ)
#define ATTN_SMEM (6 * TILE_SZ)   // 55296 bytes

__global__ __launch_bounds__(128) void attn_mma_kernel(
    const u16* __restrict__ qh, const u16* __restrict__ ql,
    u16* __restrict__ yhi, u16* __restrict__ ylo)
{
    extern __shared__ char sm_[];
    const int qt = blockIdx.x;
    const int h  = blockIdx.y;
    const int b  = blockIdx.z;
    const int tid = threadIdx.x;
    const int wid = tid >> 5;
    const int lane = tid & 31;
    const int g = lane >> 2;
    const int t = lane & 3;
    const int wm = wid * 16;

    // Load Q tile (hi/lo): 512 uint4 per array, 4 per thread.
    #pragma unroll
    for (int i = 0; i < 4; i++) {
        int slot = tid + i * 128;
        int r = slot >> 3;
        int c8 = (slot & 7) * 8;
        size_t gq = (size_t)(b * T_ + qt * 64 + r) * (3 * D_) + h * 64 + c8;
        *(uint4*)(sm_ + A_QH + r * QROWB + c8 * 2) = *(const uint4*)(qh + gq);
        *(uint4*)(sm_ + A_QL + r * QROWB + c8 * 2) = *(const uint4*)(ql + gq);
    }

    float m0 = -1e30f, m1 = -1e30f, l0 = 0.0f, l1 = 0.0f;
    float o[8][4];
    #pragma unroll
    for (int nf = 0; nf < 8; nf++)
        #pragma unroll
        for (int r = 0; r < 4; r++) o[nf][r] = 0.0f;

    for (int kt = 0; kt <= qt; kt++) {
        // Load K and V tiles (hi/lo, vectorized; V kept row-major like K)
        #pragma unroll
        for (int i = 0; i < 4; i++) {
            int slot = tid + i * 128;
            int r = slot >> 3;
            int c8 = (slot & 7) * 8;
            size_t gk = (size_t)(b * T_ + kt * 64 + r) * (3 * D_) + D_ + h * 64 + c8;
            *(uint4*)(sm_ + A_KH + r * QROWB + c8 * 2) = *(const uint4*)(qh + gk);
            *(uint4*)(sm_ + A_KL + r * QROWB + c8 * 2) = *(const uint4*)(ql + gk);
            *(uint4*)(sm_ + A_VH + r * QROWB + c8 * 2) = *(const uint4*)(qh + gk + D_);
            *(uint4*)(sm_ + A_VL + r * QROWB + c8 * 2) = *(const uint4*)(ql + gk + D_);
        }
        __syncthreads();

        // ---- S = Q @ K^T (split-3) ----
        float s[8][4];
        #pragma unroll
        for (int nf = 0; nf < 8; nf++)
            #pragma unroll
            for (int r = 0; r < 4; r++) s[nf][r] = 0.0f;

        #pragma unroll
        for (int ks = 0; ks < 4; ks++) {
            const int kb = ks * 16;
            uint32_t ah[4], al[4];
            ah[0] = *(uint32_t*)(sm_ + A_QH + (wm + g) * QROWB + (kb + t * 2) * 2);
            ah[1] = *(uint32_t*)(sm_ + A_QH + (wm + g + 8) * QROWB + (kb + t * 2) * 2);
            ah[2] = *(uint32_t*)(sm_ + A_QH + (wm + g) * QROWB + (kb + 8 + t * 2) * 2);
            ah[3] = *(uint32_t*)(sm_ + A_QH + (wm + g + 8) * QROWB + (kb + 8 + t * 2) * 2);
            al[0] = *(uint32_t*)(sm_ + A_QL + (wm + g) * QROWB + (kb + t * 2) * 2);
            al[1] = *(uint32_t*)(sm_ + A_QL + (wm + g + 8) * QROWB + (kb + t * 2) * 2);
            al[2] = *(uint32_t*)(sm_ + A_QL + (wm + g) * QROWB + (kb + 8 + t * 2) * 2);
            al[3] = *(uint32_t*)(sm_ + A_QL + (wm + g + 8) * QROWB + (kb + 8 + t * 2) * 2);
            #pragma unroll
            for (int nf = 0; nf < 8; nf++) {
                int br = nf * 8 + g;
                uint32_t bh0 = *(uint32_t*)(sm_ + A_KH + br * QROWB + (kb + t * 2) * 2);
                uint32_t bh1 = *(uint32_t*)(sm_ + A_KH + br * QROWB + (kb + 8 + t * 2) * 2);
                uint32_t bl0 = *(uint32_t*)(sm_ + A_KL + br * QROWB + (kb + t * 2) * 2);
                uint32_t bl1 = *(uint32_t*)(sm_ + A_KL + br * QROWB + (kb + 8 + t * 2) * 2);
                mma_bf16_16816(s[nf], ah[0], ah[1], ah[2], ah[3], bh0, bh1);
                mma_bf16_16816(s[nf], ah[0], ah[1], ah[2], ah[3], bl0, bl1);
                mma_bf16_16816(s[nf], al[0], al[1], al[2], al[3], bh0, bh1);
            }
        }

        // scale by 1/sqrt(DH)
        #pragma unroll
        for (int nf = 0; nf < 8; nf++)
            #pragma unroll
            for (int r = 0; r < 4; r++) s[nf][r] *= 0.125f;

        // causal mask on diagonal tile
        if (kt == qt) {
            #pragma unroll
            for (int nf = 0; nf < 8; nf++) {
                int col = nf * 8 + t * 2;
                int r0 = wm + g, r1 = wm + g + 8;
                if (col > r0)     s[nf][0] = -1e30f;
                if (col + 1 > r0) s[nf][1] = -1e30f;
                if (col > r1)     s[nf][2] = -1e30f;
                if (col + 1 > r1) s[nf][3] = -1e30f;
            }
        }

        // ---- online softmax ----
        float rm0 = -1e30f, rm1 = -1e30f;
        #pragma unroll
        for (int nf = 0; nf < 8; nf++) {
            rm0 = fmaxf(rm0, fmaxf(s[nf][0], s[nf][1]));
            rm1 = fmaxf(rm1, fmaxf(s[nf][2], s[nf][3]));
        }
        rm0 = fmaxf(rm0, __shfl_xor_sync(0xffffffffu, rm0, 1));
        rm0 = fmaxf(rm0, __shfl_xor_sync(0xffffffffu, rm0, 2));
        rm1 = fmaxf(rm1, __shfl_xor_sync(0xffffffffu, rm1, 1));
        rm1 = fmaxf(rm1, __shfl_xor_sync(0xffffffffu, rm1, 2));

        float mn0 = fmaxf(m0, rm0), mn1 = fmaxf(m1, rm1);
        float a0 = __expf(m0 - mn0), a1 = __expf(m1 - mn1);

        float rs0 = 0.0f, rs1 = 0.0f;
        uint32_t phg[8], phg8[8], plg[8], plg8[8];
        #pragma unroll
        for (int nf = 0; nf < 8; nf++) {
            float p0 = __expf(s[nf][0] - mn0);
            float p1 = __expf(s[nf][1] - mn0);
            float p2 = __expf(s[nf][2] - mn1);
            float p3 = __expf(s[nf][3] - mn1);
            rs0 += p0 + p1;
            rs1 += p2 + p3;
            phg[nf]  = split_pack(p0, p1, plg[nf]);
            phg8[nf] = split_pack(p2, p3, plg8[nf]);
        }
        rs0 += __shfl_xor_sync(0xffffffffu, rs0, 1);
        rs0 += __shfl_xor_sync(0xffffffffu, rs0, 2);
        rs1 += __shfl_xor_sync(0xffffffffu, rs1, 1);
        rs1 += __shfl_xor_sync(0xffffffffu, rs1, 2);

        l0 = l0 * a0 + rs0;
        l1 = l1 * a1 + rs1;
        m0 = mn0;
        m1 = mn1;
        #pragma unroll
        for (int nf = 0; nf < 8; nf++) {
            o[nf][0] *= a0; o[nf][1] *= a0;
            o[nf][2] *= a1; o[nf][3] *= a1;
        }

        // ---- O += P @ V (split-3) ----
        // B operand V^T assembled from row-major V via two 16-bit LDS (same
        // 4B word per lane pair -> conflict-free).
        #pragma unroll
        for (int j = 0; j < 4; j++) {
            uint32_t pa0 = phg[2 * j],     pa1 = phg8[2 * j];
            uint32_t pa2 = phg[2 * j + 1], pa3 = phg8[2 * j + 1];
            uint32_t qa0 = plg[2 * j],     qa1 = plg8[2 * j];
            uint32_t qa2 = plg[2 * j + 1], qa3 = plg8[2 * j + 1];
            int k0 = j * 16 + t * 2;
            #pragma unroll
            for (int nf = 0; nf < 8; nf++) {
                int d = nf * 8 + g;
                uint32_t h00 = *(u16*)(sm_ + A_VH + (k0)     * QROWB + d * 2);
                uint32_t h01 = *(u16*)(sm_ + A_VH + (k0 + 1) * QROWB + d * 2);
                uint32_t h10 = *(u16*)(sm_ + A_VH + (k0 + 8) * QROWB + d * 2);
                uint32_t h11 = *(u16*)(sm_ + A_VH + (k0 + 9) * QROWB + d * 2);
                uint32_t bh0 = h00 | (h01 << 16);
                uint32_t bh1 = h10 | (h11 << 16);
                uint32_t e00 = *(u16*)(sm_ + A_VL + (k0)     * QROWB + d * 2);
                uint32_t e01 = *(u16*)(sm_ + A_VL + (k0 + 1) * QROWB + d * 2);
                uint32_t e10 = *(u16*)(sm_ + A_VL + (k0 + 8) * QROWB + d * 2);
                uint32_t e11 = *(u16*)(sm_ + A_VL + (k0 + 9) * QROWB + d * 2);
                uint32_t bv0 = e00 | (e01 << 16);
                uint32_t bv1 = e10 | (e11 << 16);
                mma_bf16_16816(o[nf], pa0, pa1, pa2, pa3, bh0, bh1);
                mma_bf16_16816(o[nf], pa0, pa1, pa2, pa3, bv0, bv1);
                mma_bf16_16816(o[nf], qa0, qa1, qa2, qa3, bh0, bh1);
            }
        }
        __syncthreads();   // protect K/V smem before next tile's loads
    }

    // ---- epilogue: normalize, split to bf16 hi/lo, write y ----
    float inv0 = 1.0f / l0, inv1 = 1.0f / l1;
    #pragma unroll
    for (int nf = 0; nf < 8; nf++) {
        int col = h * 64 + nf * 8 + t * 2;
        size_t r0 = (size_t)(b * T_ + qt * 64 + wm + g) * D_ + col;
        size_t r1 = r0 + 8 * D_;
        uint32_t lp;
        uint32_t hp = split_pack(o[nf][0] * inv0, o[nf][1] * inv0, lp);
        *(uint32_t*)&yhi[r0] = hp;
        *(uint32_t*)&ylo[r0] = lp;
        hp = split_pack(o[nf][2] * inv1, o[nf][3] * inv1, lp);
        *(uint32_t*)&yhi[r1] = hp;
        *(uint32_t*)&ylo[r1] = lp;
    }
}

// ---------------------------------------------------------------------------
// Launch
// ---------------------------------------------------------------------------
extern "C" void kernel_launch(void* const* d_in, const int* in_sizes, int n_in,
                              void* d_out, int out_size)
{
    const float* x      = (const float*)d_in[0];   // [B,T,D]
    const float* w_attn = (const float*)d_in[1];   // [3D, D]
    const float* w_proj = (const float*)d_in[2];   // [D, D]
    float* out = (float*)d_out;                    // [B,T,D]

    u16 *xhi, *xlo, *wahi, *walo, *wphi, *wplo, *qkvh, *qkvl, *yhi, *ylo;
    cudaGetSymbolAddress((void**)&xhi,  g_xhi);
    cudaGetSymbolAddress((void**)&xlo,  g_xlo);
    cudaGetSymbolAddress((void**)&wahi, g_wahi);
    cudaGetSymbolAddress((void**)&walo, g_walo);
    cudaGetSymbolAddress((void**)&wphi, g_wphi);
    cudaGetSymbolAddress((void**)&wplo, g_wplo);
    cudaGetSymbolAddress((void**)&qkvh, g_qkvh);
    cudaGetSymbolAddress((void**)&qkvl, g_qkvl);
    cudaGetSymbolAddress((void**)&yhi,  g_yhi);
    cudaGetSymbolAddress((void**)&ylo,  g_ylo);

    cudaFuncSetAttribute(gemm_mma_db<true>,
                         cudaFuncAttributeMaxDynamicSharedMemorySize, GEMM_SMEM);
    cudaFuncSetAttribute(gemm_mma_db<false>,
                         cudaFuncAttributeMaxDynamicSharedMemorySize, GEMM_SMEM);
    cudaFuncSetAttribute(attn_mma_kernel,
                         cudaFuncAttributeMaxDynamicSharedMemorySize, ATTN_SMEM);

    const int M = B_ * T_;   // 8192

    // splits (x, weights only)
    split_bf16_kernel<<<(B_ * T_ * D_ / 4 + 255) / 256, 256>>>(x, xhi, xlo, B_ * T_ * D_ / 4);
    split_bf16_kernel<<<(3 * D_ * D_ / 4 + 255) / 256, 256>>>(w_attn, wahi, walo, 3 * D_ * D_ / 4);
    split_bf16_kernel<<<(D_ * D_ / 4 + 255) / 256, 256>>>(w_proj, wphi, wplo, D_ * D_ / 4);

    // 1) qkv = x @ w_attn^T -> bf16 hi/lo directly
    gemm_mma_db<true><<<dim3((3 * D_) / 128, M / 128), 256, GEMM_SMEM>>>(
        xhi, xlo, wahi, walo, nullptr, qkvh, qkvl, M, 3 * D_, D_);

    // 2) flash attention (HMMA) -> y hi/lo directly
    attn_mma_kernel<<<dim3(T_ / 64, H_, B_), 128, ATTN_SMEM>>>(qkvh, qkvl, yhi, ylo);

    // 3) out = y @ w_proj^T -> fp32
    gemm_mma_db<false><<<dim3(D_ / 128, M / 128), 256, GEMM_SMEM>>>(
        yhi, ylo, wphi, wplo, out, nullptr, nullptr, M, D_, D_);
}

// round 7
// speedup vs baseline: 3.0981x; 1.1318x over previous
#include <cuda_runtime.h>
#include <cuda_bf16.h>
#include <math.h>
#include <stdint.h>

// Problem constants
#define B_  4
#define T_  2048
#define D_  1024
#define H_  16
#define DH_ 64

typedef unsigned short u16;

// ---------------------------------------------------------------------------
// Scratch (allocation-free rule: __device__ globals)
// ---------------------------------------------------------------------------
__device__ u16 g_xhi[(size_t)B_ * T_ * D_];
__device__ u16 g_xlo[(size_t)B_ * T_ * D_];
__device__ u16 g_wahi[(size_t)3 * D_ * D_];
__device__ u16 g_walo[(size_t)3 * D_ * D_];
__device__ u16 g_wphi[(size_t)D_ * D_];
__device__ u16 g_wplo[(size_t)D_ * D_];
__device__ u16 g_qkvh[(size_t)B_ * T_ * 3 * D_];
__device__ u16 g_qkvl[(size_t)B_ * T_ * 3 * D_];
__device__ u16 g_yhi[(size_t)B_ * T_ * D_];
__device__ u16 g_ylo[(size_t)B_ * T_ * D_];

// ---------------------------------------------------------------------------
// Helpers
// ---------------------------------------------------------------------------
__device__ __forceinline__ uint32_t smem_u32(const void* p) {
    uint32_t a;
    asm("{ .reg .u64 t; cvta.to.shared.u64 t, %1; cvt.u32.u64 %0, t; }"
        : "=r"(a) : "l"(p));
    return a;
}

__device__ __forceinline__ void mma_bf16_16816(
    float c[4], uint32_t a0, uint32_t a1, uint32_t a2, uint32_t a3,
    uint32_t b0, uint32_t b1)
{
    asm volatile(
        "mma.sync.aligned.m16n8k16.row.col.f32.bf16.bf16.f32 "
        "{%0,%1,%2,%3}, {%4,%5,%6,%7}, {%8,%9}, {%0,%1,%2,%3};"
        : "+f"(c[0]), "+f"(c[1]), "+f"(c[2]), "+f"(c[3])
        : "r"(a0), "r"(a1), "r"(a2), "r"(a3), "r"(b0), "r"(b1));
}

#define LDMX4(r, addr) \
    asm volatile("ldmatrix.sync.aligned.m8n8.x4.shared.b16 {%0,%1,%2,%3}, [%4];" \
        : "=r"((r)[0]), "=r"((r)[1]), "=r"((r)[2]), "=r"((r)[3]) : "r"(addr))
#define LDMX4T(r, addr) \
    asm volatile("ldmatrix.sync.aligned.m8n8.x4.trans.shared.b16 {%0,%1,%2,%3}, [%4];" \
        : "=r"((r)[0]), "=r"((r)[1]), "=r"((r)[2]), "=r"((r)[3]) : "r"(addr))

__device__ __forceinline__ uint32_t split_pack(float f0, float f1, uint32_t& lop) {
    __nv_bfloat16 h0 = __float2bfloat16(f0);
    __nv_bfloat16 h1 = __float2bfloat16(f1);
    __nv_bfloat16 l0 = __float2bfloat16(f0 - __bfloat162float(h0));
    __nv_bfloat16 l1 = __float2bfloat16(f1 - __bfloat162float(h1));
    lop = (uint32_t)__bfloat16_as_ushort(l0) | ((uint32_t)__bfloat16_as_ushort(l1) << 16);
    return (uint32_t)__bfloat16_as_ushort(h0) | ((uint32_t)__bfloat16_as_ushort(h1) << 16);
}

#define CP_ASYNC16(dst, src) \
    asm volatile("cp.async.cg.shared.global [%0], [%1], 16;" :: "r"(dst), "l"(src))
#define CP_COMMIT() asm volatile("cp.async.commit_group;")
#define CP_WAIT1()  asm volatile("cp.async.wait_group 1;")
#define CP_WAIT0()  asm volatile("cp.async.wait_group 0;")

// ---------------------------------------------------------------------------
// Split fp32 -> bf16 (hi, lo) pair
// ---------------------------------------------------------------------------
__global__ __launch_bounds__(256) void split_bf16_kernel(
    const float* __restrict__ in, u16* __restrict__ hi,
    u16* __restrict__ lo, int n4)
{
    int i = blockIdx.x * 256 + threadIdx.x;
    if (i >= n4) return;
    float4 v = ((const float4*)in)[i];
    uint32_t lp0, lp1;
    uint32_t hp0 = split_pack(v.x, v.y, lp0);
    uint32_t hp1 = split_pack(v.z, v.w, lp1);
    ((uint2*)hi)[i] = make_uint2(hp0, hp1);
    ((uint2*)lo)[i] = make_uint2(lp0, lp1);
}

// ---------------------------------------------------------------------------
// HMMA GEMM, cp.async double-buffered, ldmatrix fragment loads.
// C[M,N] = A[M,K] @ B[N,K]^T with hi/lo split accumulation (3 passes).
// Block tile 128x128, BK=32, 256 threads = 8 warps (2x4), warp tile 64x32.
// ---------------------------------------------------------------------------
#define KPADB 80          // bytes per smem row (40 shorts)
#define ARR_SZ 10240      // 128 * 80
#define STAGE_SZ 40960
#define GEMM_SMEM (2 * STAGE_SZ)

template<bool SPLIT_OUT>
__global__ __launch_bounds__(256) void gemm_mma_db(
    const u16* __restrict__ Ahi, const u16* __restrict__ Alo,
    const u16* __restrict__ Bhi, const u16* __restrict__ Blo,
    float* __restrict__ Cf, u16* __restrict__ Chi, u16* __restrict__ Clo,
    int M, int N, int K)
{
    extern __shared__ char smc[];
    const uint32_t sb = smem_u32(smc);

    const int tid = threadIdx.x;
    const int wid = tid >> 5;
    const int lane = tid & 31;
    const int g = lane >> 2;
    const int t = lane & 3;
    const int warp_m = (wid >> 2) * 64;
    const int warp_n = (wid & 3) * 32;
    const int bm = blockIdx.y * 128;
    const int bn = blockIdx.x * 128;

    // ldmatrix per-lane row/col selectors
    const int a_r = (lane & 7) + ((lane >> 3) & 1) * 8;  // A: row within 16
    const int a_k = (lane >> 4) * 8;                     // A: k offset 0/8
    const int b_r = (lane & 7) + (lane >> 4) * 8;        // B: row within 16
    const int b_k = ((lane >> 3) & 1) * 8;               // B: k offset 0/8

    float acc[4][4][4];
    #pragma unroll
    for (int i = 0; i < 4; i++)
        #pragma unroll
        for (int j = 0; j < 4; j++)
            #pragma unroll
            for (int r = 0; r < 4; r++) acc[i][j][r] = 0.0f;

    auto prefetch = [&](int k0, int s) {
        #pragma unroll
        for (int c = 0; c < 2; c++) {
            int ch = tid + c * 256;
            int row = ch >> 2;
            int cq = ch & 3;
            uint32_t so = sb + s * STAGE_SZ + row * KPADB + cq * 16;
            size_t ga = (size_t)(bm + row) * K + k0 + cq * 8;
            size_t gb = (size_t)(bn + row) * K + k0 + cq * 8;
            CP_ASYNC16(so + 0 * ARR_SZ, Ahi + ga);
            CP_ASYNC16(so + 1 * ARR_SZ, Alo + ga);
            CP_ASYNC16(so + 2 * ARR_SZ, Bhi + gb);
            CP_ASYNC16(so + 3 * ARR_SZ, Blo + gb);
        }
        CP_COMMIT();
    };

    const int nt = K / 32;
    prefetch(0, 0);

    for (int ti = 0; ti < nt; ti++) {
        if (ti + 1 < nt) { prefetch((ti + 1) * 32, (ti + 1) & 1); CP_WAIT1(); }
        else             { CP_WAIT0(); }
        __syncthreads();

        const uint32_t st = sb + (ti & 1) * STAGE_SZ;
        const uint32_t sAh = st + 0 * ARR_SZ;
        const uint32_t sAl = st + 1 * ARR_SZ;
        const uint32_t sBh = st + 2 * ARR_SZ;
        const uint32_t sBl = st + 3 * ARR_SZ;

        #pragma unroll
        for (int ks = 0; ks < 2; ks++) {
            const int kb = ks * 16;

            uint32_t ah[4][4], al[4][4], bh[2][4], bl[2][4];
            #pragma unroll
            for (int mf = 0; mf < 4; mf++) {
                uint32_t off = (uint32_t)(warp_m + mf * 16 + a_r) * KPADB
                             + (uint32_t)(kb + a_k) * 2;
                LDMX4(ah[mf], sAh + off);
                LDMX4(al[mf], sAl + off);
            }
            #pragma unroll
            for (int nf2 = 0; nf2 < 2; nf2++) {
                uint32_t off = (uint32_t)(warp_n + nf2 * 16 + b_r) * KPADB
                             + (uint32_t)(kb + b_k) * 2;
                LDMX4(bh[nf2], sBh + off);
                LDMX4(bl[nf2], sBl + off);
            }

            // pass 1: hi*hi
            #pragma unroll
            for (int mf = 0; mf < 4; mf++)
                #pragma unroll
                for (int nf = 0; nf < 4; nf++)
                    mma_bf16_16816(acc[mf][nf],
                                   ah[mf][0], ah[mf][1], ah[mf][2], ah[mf][3],
                                   bh[nf >> 1][(nf & 1) * 2],
                                   bh[nf >> 1][(nf & 1) * 2 + 1]);
            // pass 2: hi*lo
            #pragma unroll
            for (int mf = 0; mf < 4; mf++)
                #pragma unroll
                for (int nf = 0; nf < 4; nf++)
                    mma_bf16_16816(acc[mf][nf],
                                   ah[mf][0], ah[mf][1], ah[mf][2], ah[mf][3],
                                   bl[nf >> 1][(nf & 1) * 2],
                                   bl[nf >> 1][(nf & 1) * 2 + 1]);
            // pass 3: lo*hi
            #pragma unroll
            for (int mf = 0; mf < 4; mf++)
                #pragma unroll
                for (int nf = 0; nf < 4; nf++)
                    mma_bf16_16816(acc[mf][nf],
                                   al[mf][0], al[mf][1], al[mf][2], al[mf][3],
                                   bh[nf >> 1][(nf & 1) * 2],
                                   bh[nf >> 1][(nf & 1) * 2 + 1]);
        }
        __syncthreads();
    }

    #pragma unroll
    for (int mf = 0; mf < 4; mf++) {
        #pragma unroll
        for (int nf = 0; nf < 4; nf++) {
            int row = bm + warp_m + mf * 16 + g;
            int col = bn + warp_n + nf * 8 + t * 2;
            if (SPLIT_OUT) {
                uint32_t lp;
                uint32_t hp = split_pack(acc[mf][nf][0], acc[mf][nf][1], lp);
                *(uint32_t*)&Chi[(size_t)row * N + col] = hp;
                *(uint32_t*)&Clo[(size_t)row * N + col] = lp;
                hp = split_pack(acc[mf][nf][2], acc[mf][nf][3], lp);
                *(uint32_t*)&Chi[(size_t)(row + 8) * N + col] = hp;
                *(uint32_t*)&Clo[(size_t)(row + 8) * N + col] = lp;
            } else {
                *(float2*)(Cf + (size_t)row * N + col) =
                    make_float2(acc[mf][nf][0], acc[mf][nf][1]);
                *(float2*)(Cf + (size_t)(row + 8) * N + col) =
                    make_float2(acc[mf][nf][2], acc[mf][nf][3]);
            }
        }
    }
}

// ---------------------------------------------------------------------------
// Flash attention on HMMA, ldmatrix fragment loads, hi/lo split.
// Block: 128 threads (4 warps); warp w owns q rows w*16..w*16+15.
// ---------------------------------------------------------------------------
#define QROWB 144                 // 72 shorts per padded row
#define TILE_SZ (64 * QROWB)      // 9216 bytes
#define A_QH (0 * TILE_SZ)
#define A_QL (1 * TILE_SZ)
#define A_KH (2 * TILE_SZ)
#define A_KL (3 * TILE_SZ)
#define A_VH (4 * TILE_SZ)
#define A_VL (5 * TILE_SZ)
#define ATTN_SMEM (6 * TILE_SZ)   // 55296 bytes

__global__ __launch_bounds__(128) void attn_mma_kernel(
    const u16* __restrict__ qh, const u16* __restrict__ ql,
    u16* __restrict__ yhi, u16* __restrict__ ylo)
{
    extern __shared__ char sm_[];
    const uint32_t sbase = smem_u32(sm_);
    const int qt = blockIdx.x;
    const int h  = blockIdx.y;
    const int b  = blockIdx.z;
    const int tid = threadIdx.x;
    const int wid = tid >> 5;
    const int lane = tid & 31;
    const int g = lane >> 2;
    const int t = lane & 3;
    const int wm = wid * 16;

    const int a_r = (lane & 7) + ((lane >> 3) & 1) * 8;
    const int a_k = (lane >> 4) * 8;
    const int b_r = (lane & 7) + (lane >> 4) * 8;
    const int b_k = ((lane >> 3) & 1) * 8;

    // Load Q tile (hi/lo) via cp.async
    #pragma unroll
    for (int i = 0; i < 4; i++) {
        int slot = tid + i * 128;
        int r = slot >> 3;
        int c8 = (slot & 7) * 8;
        size_t gq = (size_t)(b * T_ + qt * 64 + r) * (3 * D_) + h * 64 + c8;
        uint32_t so = sbase + r * QROWB + c8 * 2;
        CP_ASYNC16(so + A_QH, qh + gq);
        CP_ASYNC16(so + A_QL, ql + gq);
    }
    CP_COMMIT();

    float m0 = -1e30f, m1 = -1e30f, l0 = 0.0f, l1 = 0.0f;
    float o[8][4];
    #pragma unroll
    for (int nf = 0; nf < 8; nf++)
        #pragma unroll
        for (int r = 0; r < 4; r++) o[nf][r] = 0.0f;

    for (int kt = 0; kt <= qt; kt++) {
        // Load K and V tiles (hi/lo) via cp.async
        #pragma unroll
        for (int i = 0; i < 4; i++) {
            int slot = tid + i * 128;
            int r = slot >> 3;
            int c8 = (slot & 7) * 8;
            size_t gk = (size_t)(b * T_ + kt * 64 + r) * (3 * D_) + D_ + h * 64 + c8;
            uint32_t so = sbase + r * QROWB + c8 * 2;
            CP_ASYNC16(so + A_KH, qh + gk);
            CP_ASYNC16(so + A_KL, ql + gk);
            CP_ASYNC16(so + A_VH, qh + gk + D_);
            CP_ASYNC16(so + A_VL, ql + gk + D_);
        }
        CP_COMMIT();
        CP_WAIT0();
        __syncthreads();

        // ---- S = Q @ K^T (split-3, ldmatrix) ----
        float s[8][4];
        #pragma unroll
        for (int nf = 0; nf < 8; nf++)
            #pragma unroll
            for (int r = 0; r < 4; r++) s[nf][r] = 0.0f;

        #pragma unroll
        for (int ks = 0; ks < 4; ks++) {
            const int kb = ks * 16;
            uint32_t ah[4], al[4], kh[4][4], kl[4][4];
            {
                uint32_t off = (uint32_t)(wm + a_r) * QROWB + (uint32_t)(kb + a_k) * 2;
                LDMX4(ah, sbase + A_QH + off);
                LDMX4(al, sbase + A_QL + off);
            }
            #pragma unroll
            for (int nf2 = 0; nf2 < 4; nf2++) {
                uint32_t off = (uint32_t)(nf2 * 16 + b_r) * QROWB
                             + (uint32_t)(kb + b_k) * 2;
                LDMX4(kh[nf2], sbase + A_KH + off);
                LDMX4(kl[nf2], sbase + A_KL + off);
            }
            #pragma unroll
            for (int nf = 0; nf < 8; nf++)
                mma_bf16_16816(s[nf], ah[0], ah[1], ah[2], ah[3],
                               kh[nf >> 1][(nf & 1) * 2], kh[nf >> 1][(nf & 1) * 2 + 1]);
            #pragma unroll
            for (int nf = 0; nf < 8; nf++)
                mma_bf16_16816(s[nf], ah[0], ah[1], ah[2], ah[3],
                               kl[nf >> 1][(nf & 1) * 2], kl[nf >> 1][(nf & 1) * 2 + 1]);
            #pragma unroll
            for (int nf = 0; nf < 8; nf++)
                mma_bf16_16816(s[nf], al[0], al[1], al[2], al[3],
                               kh[nf >> 1][(nf & 1) * 2], kh[nf >> 1][(nf & 1) * 2 + 1]);
        }

        #pragma unroll
        for (int nf = 0; nf < 8; nf++)
            #pragma unroll
            for (int r = 0; r < 4; r++) s[nf][r] *= 0.125f;

        if (kt == qt) {
            #pragma unroll
            for (int nf = 0; nf < 8; nf++) {
                int col = nf * 8 + t * 2;
                int r0 = wm + g, r1 = wm + g + 8;
                if (col > r0)     s[nf][0] = -1e30f;
                if (col + 1 > r0) s[nf][1] = -1e30f;
                if (col > r1)     s[nf][2] = -1e30f;
                if (col + 1 > r1) s[nf][3] = -1e30f;
            }
        }

        // ---- online softmax ----
        float rm0 = -1e30f, rm1 = -1e30f;
        #pragma unroll
        for (int nf = 0; nf < 8; nf++) {
            rm0 = fmaxf(rm0, fmaxf(s[nf][0], s[nf][1]));
            rm1 = fmaxf(rm1, fmaxf(s[nf][2], s[nf][3]));
        }
        rm0 = fmaxf(rm0, __shfl_xor_sync(0xffffffffu, rm0, 1));
        rm0 = fmaxf(rm0, __shfl_xor_sync(0xffffffffu, rm0, 2));
        rm1 = fmaxf(rm1, __shfl_xor_sync(0xffffffffu, rm1, 1));
        rm1 = fmaxf(rm1, __shfl_xor_sync(0xffffffffu, rm1, 2));

        float mn0 = fmaxf(m0, rm0), mn1 = fmaxf(m1, rm1);
        float a0 = __expf(m0 - mn0), a1 = __expf(m1 - mn1);

        float rs0 = 0.0f, rs1 = 0.0f;
        uint32_t phg[8], phg8[8], plg[8], plg8[8];
        #pragma unroll
        for (int nf = 0; nf < 8; nf++) {
            float p0 = __expf(s[nf][0] - mn0);
            float p1 = __expf(s[nf][1] - mn0);
            float p2 = __expf(s[nf][2] - mn1);
            float p3 = __expf(s[nf][3] - mn1);
            rs0 += p0 + p1;
            rs1 += p2 + p3;
            phg[nf]  = split_pack(p0, p1, plg[nf]);
            phg8[nf] = split_pack(p2, p3, plg8[nf]);
        }
        rs0 += __shfl_xor_sync(0xffffffffu, rs0, 1);
        rs0 += __shfl_xor_sync(0xffffffffu, rs0, 2);
        rs1 += __shfl_xor_sync(0xffffffffu, rs1, 1);
        rs1 += __shfl_xor_sync(0xffffffffu, rs1, 2);

        l0 = l0 * a0 + rs0;
        l1 = l1 * a1 + rs1;
        m0 = mn0;
        m1 = mn1;
        #pragma unroll
        for (int nf = 0; nf < 8; nf++) {
            o[nf][0] *= a0; o[nf][1] *= a0;
            o[nf][2] *= a1; o[nf][3] *= a1;
        }

        // ---- O += P @ V (split-3, ldmatrix.trans for V^T) ----
        #pragma unroll
        for (int j = 0; j < 4; j++) {
            const int k0 = j * 16;
            uint32_t vh[4][4], vl[4][4];
            #pragma unroll
            for (int nf2 = 0; nf2 < 4; nf2++) {
                uint32_t off = (uint32_t)(k0 + a_r) * QROWB
                             + (uint32_t)(nf2 * 16 + a_k) * 2;
                LDMX4T(vh[nf2], sbase + A_VH + off);
                LDMX4T(vl[nf2], sbase + A_VL + off);
            }
            uint32_t pa0 = phg[2 * j],     pa1 = phg8[2 * j];
            uint32_t pa2 = phg[2 * j + 1], pa3 = phg8[2 * j + 1];
            uint32_t qa0 = plg[2 * j],     qa1 = plg8[2 * j];
            uint32_t qa2 = plg[2 * j + 1], qa3 = plg8[2 * j + 1];
            #pragma unroll
            for (int nf = 0; nf < 8; nf++)
                mma_bf16_16816(o[nf], pa0, pa1, pa2, pa3,
                               vh[nf >> 1][(nf & 1) * 2], vh[nf >> 1][(nf & 1) * 2 + 1]);
            #pragma unroll
            for (int nf = 0; nf < 8; nf++)
                mma_bf16_16816(o[nf], pa0, pa1, pa2, pa3,
                               vl[nf >> 1][(nf & 1) * 2], vl[nf >> 1][(nf & 1) * 2 + 1]);
            #pragma unroll
            for (int nf = 0; nf < 8; nf++)
                mma_bf16_16816(o[nf], qa0, qa1, qa2, qa3,
                               vh[nf >> 1][(nf & 1) * 2], vh[nf >> 1][(nf & 1) * 2 + 1]);
        }
        __syncthreads();   // protect K/V smem before next tile's loads
    }

    // ---- epilogue ----
    float inv0 = 1.0f / l0, inv1 = 1.0f / l1;
    #pragma unroll
    for (int nf = 0; nf < 8; nf++) {
        int col = h * 64 + nf * 8 + t * 2;
        size_t r0 = (size_t)(b * T_ + qt * 64 + wm + g) * D_ + col;
        size_t r1 = r0 + 8 * D_;
        uint32_t lp;
        uint32_t hp = split_pack(o[nf][0] * inv0, o[nf][1] * inv0, lp);
        *(uint32_t*)&yhi[r0] = hp;
        *(uint32_t*)&ylo[r0] = lp;
        hp = split_pack(o[nf][2] * inv1, o[nf][3] * inv1, lp);
        *(uint32_t*)&yhi[r1] = hp;
        *(uint32_t*)&ylo[r1] = lp;
    }
}

// ---------------------------------------------------------------------------
// Launch
// ---------------------------------------------------------------------------
extern "C" void kernel_launch(void* const* d_in, const int* in_sizes, int n_in,
                              void* d_out, int out_size)
{
    const float* x      = (const float*)d_in[0];
    const float* w_attn = (const float*)d_in[1];
    const float* w_proj = (const float*)d_in[2];
    float* out = (float*)d_out;

    u16 *xhi, *xlo, *wahi, *walo, *wphi, *wplo, *qkvh, *qkvl, *yhi, *ylo;
    cudaGetSymbolAddress((void**)&xhi,  g_xhi);
    cudaGetSymbolAddress((void**)&xlo,  g_xlo);
    cudaGetSymbolAddress((void**)&wahi, g_wahi);
    cudaGetSymbolAddress((void**)&walo, g_walo);
    cudaGetSymbolAddress((void**)&wphi, g_wphi);
    cudaGetSymbolAddress((void**)&wplo, g_wplo);
    cudaGetSymbolAddress((void**)&qkvh, g_qkvh);
    cudaGetSymbolAddress((void**)&qkvl, g_qkvl);
    cudaGetSymbolAddress((void**)&yhi,  g_yhi);
    cudaGetSymbolAddress((void**)&ylo,  g_ylo);

    cudaFuncSetAttribute(gemm_mma_db<true>,
                         cudaFuncAttributeMaxDynamicSharedMemorySize, GEMM_SMEM);
    cudaFuncSetAttribute(gemm_mma_db<false>,
                         cudaFuncAttributeMaxDynamicSharedMemorySize, GEMM_SMEM);
    cudaFuncSetAttribute(attn_mma_kernel,
                         cudaFuncAttributeMaxDynamicSharedMemorySize, ATTN_SMEM);

    const int M = B_ * T_;   // 8192

    split_bf16_kernel<<<(B_ * T_ * D_ / 4 + 255) / 256, 256>>>(x, xhi, xlo, B_ * T_ * D_ / 4);
    split_bf16_kernel<<<(3 * D_ * D_ / 4 + 255) / 256, 256>>>(w_attn, wahi, walo, 3 * D_ * D_ / 4);
    split_bf16_kernel<<<(D_ * D_ / 4 + 255) / 256, 256>>>(w_proj, wphi, wplo, D_ * D_ / 4);

    gemm_mma_db<true><<<dim3((3 * D_) / 128, M / 128), 256, GEMM_SMEM>>>(
        xhi, xlo, wahi, walo, nullptr, qkvh, qkvl, M, 3 * D_, D_);

    attn_mma_kernel<<<dim3(T_ / 64, H_, B_), 128, ATTN_SMEM>>>(qkvh, qkvl, yhi, ylo);

    gemm_mma_db<false><<<dim3(D_ / 128, M / 128), 256, GEMM_SMEM>>>(
        yhi, ylo, wphi, wplo, out, nullptr, nullptr, M, D_, D_);
}